// round 17
// baseline (speedup 1.0000x reference)
#include <cuda_runtime.h>
#include <cuda_fp16.h>
#include <cstdint>

#define BATCH 2
#define SEQ   2048
#define CH    768
#define HEADS 12
#define HDIM  64
#define ATT_SCALE 0.125f    // HDIM^-0.5
#define OA_SCALE 4096.0f
#define OA_INV   (1.0f / 4096.0f)

// ---------------- scratch (static device arrays; no cudaMalloc) -------------
__device__ float g_xpart[BATCH * 128 * CH];
__device__ float g_xmean2[BATCH * 8 * CH];
__device__ float g_kavg[BATCH * HEADS * HDIM];
__device__ float g_u[BATCH * HEADS * CH];
__device__ float g_z[BATCH * HEADS * SEQ];
__device__ float g_attn[BATCH * HEADS * SEQ];

__device__ __half g_xhi[BATCH * SEQ * CH];
__device__ __half g_wvhi[CH * CH];
__device__ __half g_wphi[CH * CH];
__device__ __half g_vhi[BATCH * SEQ * CH];
__device__ __half g_oahi[BATCH * SEQ * CH];

// ---------------- fused: x -> fp16 hi + 16-row partial sums -----------------
__global__ void xhi_part_kernel(const float* __restrict__ x) {
    int b = blockIdx.y;
    int chunk = blockIdx.x;           // 0..127
    int c = threadIdx.x;              // 768 threads
    size_t base = ((size_t)b * SEQ + (size_t)chunk * 16) * CH + c;
    float s = 0.f;
    #pragma unroll
    for (int n = 0; n < 16; n++) {
        float v = x[base + (size_t)n * CH];
        s += v;
        g_xhi[base + (size_t)n * CH] = __float2half_rn(v);
    }
    g_xpart[(b * 128 + chunk) * CH + c] = s;
}

// ---------------- fused: Wv and Wp -> fp16 hi --------------------------------
__global__ void wvp_hi_kernel(const float* __restrict__ Wv,
                              const float* __restrict__ Wp, int n4) {
    int i = blockIdx.x * 256 + threadIdx.x;
    if (i >= n4) return;
    const float* src = blockIdx.y ? Wp : Wv;
    __half* dst = blockIdx.y ? g_wphi : g_wvhi;
    float4 v = ((const float4*)src)[i];
    ((__half2*)dst)[i * 2]     = __halves2half2(__float2half_rn(v.x), __float2half_rn(v.y));
    ((__half2*)dst)[i * 2 + 1] = __halves2half2(__float2half_rn(v.z), __float2half_rn(v.w));
}

// ---------------- xmean stage 2: 16 partials -> 1 sub-partial ---------------
__global__ void xmean2_kernel() {
    int b = blockIdx.y;
    int grp = blockIdx.x;             // 0..7
    int c = threadIdx.x;
    float s = 0.f;
    #pragma unroll
    for (int k = 0; k < 16; k++)
        s += g_xpart[(b * 128 + grp * 16 + k) * CH + c];
    g_xmean2[(b * 8 + grp) * CH + c] = s;
}

// ---------------- kavg[b,h,d] = xmean[b,:] . Wk[h*64+d,:] --------------------
__global__ void kavg_kernel(const float* __restrict__ Wk) {
    int b = blockIdx.x / HEADS;
    int h = blockIdx.x % HEADS;
    __shared__ float xm[CH];
    for (int c = threadIdx.x; c < CH; c += 256) {
        float s = 0.f;
        #pragma unroll
        for (int grp = 0; grp < 8; grp++)
            s += g_xmean2[(b * 8 + grp) * CH + c];
        xm[c] = s * (1.0f / SEQ);
    }
    __syncthreads();
    int d = threadIdx.x >> 2;
    int sub = threadIdx.x & 3;
    const float* wk = Wk + (size_t)(h * HDIM + d) * CH;
    float s = 0.f;
    #pragma unroll 8
    for (int c = sub; c < CH; c += 4) s += xm[c] * wk[c];
    s += __shfl_down_sync(0xffffffffu, s, 2);
    s += __shfl_down_sync(0xffffffffu, s, 1);
    if (sub == 0) g_kavg[(b * HEADS + h) * HDIM + d] = s;
}

// ---------------- u[b,h,c] = SCALE * sum_d Wq[h*64+d,c] * kavg[b,h,d] -------
__global__ void u2_kernel(const float* __restrict__ Wq) {
    int bh = blockIdx.y;
    int h = bh % HEADS;
    int c = blockIdx.x * 256 + threadIdx.x;
    __shared__ float ka[HDIM];
    if (threadIdx.x < HDIM) ka[threadIdx.x] = g_kavg[bh * HDIM + threadIdx.x];
    __syncthreads();
    const float* wq = Wq + (size_t)(h * HDIM) * CH + c;
    float s = 0.f;
    #pragma unroll 16
    for (int d = 0; d < HDIM; d++) s += wq[(size_t)d * CH] * ka[d];
    g_u[bh * CH + c] = s * ATT_SCALE;
}

// ---------------- z[b,h,n] = x[b,n,:] . u[b,h,:]  (8 rows/block) -------------
__global__ void __launch_bounds__(256) z_kernel(const float* __restrict__ x) {
    __shared__ float us[HEADS * CH];
    int b = blockIdx.y;
    int tid = threadIdx.x;
    for (int i = tid; i < HEADS * CH; i += 256) us[i] = g_u[b * HEADS * CH + i];
    __syncthreads();
    int wid = tid >> 5, lane = tid & 31;
    int n = blockIdx.x * 8 + wid;
    const float* xr = x + ((size_t)b * SEQ + n) * CH;
    float xv[24];
    #pragma unroll
    for (int i = 0; i < 24; i++) xv[i] = xr[lane + i * 32];
    #pragma unroll
    for (int h = 0; h < HEADS; h++) {
        const float* uh = us + h * CH;
        float s = 0.f;
        #pragma unroll
        for (int i = 0; i < 24; i++) s += xv[i] * uh[lane + i * 32];
        #pragma unroll
        for (int off = 16; off > 0; off >>= 1)
            s += __shfl_down_sync(0xffffffffu, s, off);
        if (lane == 0) g_z[(b * HEADS + h) * SEQ + n] = s;
    }
}

// ---------------- softmax over n per (b,h), fold 1/SEQ ------------------------
__global__ void softmax_kernel() {
    __shared__ float red[256];
    int base = blockIdx.x * SEQ;
    int tid = threadIdx.x;
    float v[8];
    float m = -1e30f;
    #pragma unroll
    for (int k = 0; k < 8; k++) {
        v[k] = g_z[base + tid + k * 256];
        m = fmaxf(m, v[k]);
    }
    red[tid] = m; __syncthreads();
    for (int s = 128; s > 0; s >>= 1) {
        if (tid < s) red[tid] = fmaxf(red[tid], red[tid + s]);
        __syncthreads();
    }
    m = red[0]; __syncthreads();
    float sum = 0.f;
    #pragma unroll
    for (int k = 0; k < 8; k++) { v[k] = __expf(v[k] - m); sum += v[k]; }
    red[tid] = sum; __syncthreads();
    for (int s = 128; s > 0; s >>= 1) {
        if (tid < s) red[tid] += red[tid + s];
        __syncthreads();
    }
    float inv = 1.0f / (red[0] * (float)SEQ);
    #pragma unroll
    for (int k = 0; k < 8; k++) g_attn[base + tid + k * 256] = v[k] * inv;
}

// ================= warp-MMA building blocks ==================================
__device__ __forceinline__ void mma16816(float* c, const uint32_t* a, const uint32_t* b) {
    asm volatile(
        "mma.sync.aligned.m16n8k16.row.col.f32.f16.f16.f32 "
        "{%0,%1,%2,%3}, {%4,%5,%6,%7}, {%8,%9}, {%0,%1,%2,%3};\n"
        : "+f"(c[0]), "+f"(c[1]), "+f"(c[2]), "+f"(c[3])
        : "r"(a[0]), "r"(a[1]), "r"(a[2]), "r"(a[3]), "r"(b[0]), "r"(b[1]));
}

__device__ __forceinline__ uint32_t smem_u32(const void* p) {
    uint32_t a;
    asm("{ .reg .u64 t; cvta.to.shared.u64 t, %1; cvt.u32.u64 %0, t; }"
        : "=r"(a) : "l"(p));
    return a;
}

__device__ __forceinline__ void ldmatrix_x4(uint32_t* r, uint32_t addr) {
    asm volatile(
        "ldmatrix.sync.aligned.m8n8.x4.shared.b16 {%0,%1,%2,%3}, [%4];"
        : "=r"(r[0]), "=r"(r[1]), "=r"(r[2]), "=r"(r[3]) : "r"(addr));
}

__device__ __forceinline__ void ldmatrix_x4_trans(uint32_t* r, uint32_t addr) {
    asm volatile(
        "ldmatrix.sync.aligned.m8n8.x4.trans.shared.b16 {%0,%1,%2,%3}, [%4];"
        : "=r"(r[0]), "=r"(r[1]), "=r"(r[2]), "=r"(r[3]) : "r"(addr));
}

__device__ __forceinline__ void cp_async16(uint32_t smem_addr, const void* gptr) {
    asm volatile("cp.async.cg.shared.global [%0], [%1], 16;"
                 :: "r"(smem_addr), "l"(gptr) : "memory");
}
#define CP_COMMIT()  asm volatile("cp.async.commit_group;" ::: "memory")
#define CP_WAIT(N)   asm volatile("cp.async.wait_group %0;" :: "n"(N) : "memory")

// ================= warp-MMA fp16 GEMM: 64x128 tile, 3 CTAs/SM ================
// moff: row offset (for batch-split out-proj halves).
#define GEMM_STAGE_BYTES 15360
#define GEMM_SMEM_BYTES  (4 * GEMM_STAGE_BYTES)

template <int MODE>
__global__ void __launch_bounds__(256, 3) gemm_mma_kernel(
    const __half* __restrict__ Ahi,
    const __half* __restrict__ Bhi,
    const float* __restrict__ bias, float* __restrict__ out,
    __half* __restrict__ outhi, float outscale, int moff)
{
    extern __shared__ uint32_t dsm[];
    uint32_t sbase = smem_u32(dsm);

    int tid = threadIdx.x;
    int m0 = blockIdx.y * 64 + moff;
    int n0 = blockIdx.x * 128;
    int w = tid >> 5, lane = tid & 31;
    int wm = w >> 2, wn = w & 3;
    int g = lane >> 2, tig = lane & 3;

    float acc[2][4][4];
    #pragma unroll
    for (int mt = 0; mt < 2; mt++)
        #pragma unroll
        for (int nt = 0; nt < 4; nt++)
            #pragma unroll
            for (int r = 0; r < 4; r++) acc[mt][nt][r] = 0.f;

    int lrow = tid >> 2;
    int q = tid & 3;
    uint32_t sdstA  = (uint32_t)(lrow * 80 + q * 16);
    uint32_t sdstB0 = (uint32_t)(5120 + lrow * 80 + q * 16);
    uint32_t sdstB1 = (uint32_t)(5120 + (lrow + 64) * 80 + q * 16);
    size_t goffA  = (size_t)(m0 + lrow) * CH + q * 8;
    size_t goffB0 = (size_t)(n0 + lrow) * CH + q * 8;
    size_t goffB1 = (size_t)(n0 + lrow + 64) * CH + q * 8;

    int sub = lane >> 3, lr = lane & 7;
    int aRow = wm * 32 + ((sub & 1) << 3) + lr;
    int aKs  = sub >> 1;
    uint32_t aOffBase = (uint32_t)(aRow * 80 + aKs * 16);
    int bRow = wn * 32 + (((sub >> 1) & 1) << 3) + lr;
    int bKs  = sub & 1;
    uint32_t bOffBase = (uint32_t)(5120 + bRow * 80 + bKs * 16);

    const int NSTAGE = CH / 32;   // 24

    #pragma unroll
    for (int p = 0; p < 3; p++) {
        uint32_t st = sbase + (uint32_t)p * GEMM_STAGE_BYTES;
        size_t ka = (size_t)p * 32;
        cp_async16(st + sdstA,  Ahi + goffA + ka);
        cp_async16(st + sdstB0, Bhi + goffB0 + ka);
        cp_async16(st + sdstB1, Bhi + goffB1 + ka);
        CP_COMMIT();
    }

    for (int s = 0; s < NSTAGE; s++) {
        if (s + 2 < NSTAGE)      { CP_WAIT(2); }
        else if (s + 1 < NSTAGE) { CP_WAIT(1); }
        else                     { CP_WAIT(0); }
        __syncthreads();

        if (s + 3 < NSTAGE) {
            uint32_t st2 = sbase + (uint32_t)((s + 3) & 3) * GEMM_STAGE_BYTES;
            size_t ka = (size_t)(s + 3) * 32;
            cp_async16(st2 + sdstA,  Ahi + goffA + ka);
            cp_async16(st2 + sdstB0, Bhi + goffB0 + ka);
            cp_async16(st2 + sdstB1, Bhi + goffB1 + ka);
            CP_COMMIT();
        }

        uint32_t st = sbase + (uint32_t)(s & 3) * GEMM_STAGE_BYTES;

        #pragma unroll
        for (int kk = 0; kk < 2; kk++) {
            uint32_t kadd = (uint32_t)(kk * 32);
            uint32_t bh[4][2];
            #pragma unroll
            for (int np = 0; np < 2; np++) {
                uint32_t r4[4];
                ldmatrix_x4(r4, st + bOffBase + kadd + (uint32_t)(np * 16 * 80));
                bh[np * 2][0] = r4[0];      bh[np * 2][1] = r4[1];
                bh[np * 2 + 1][0] = r4[2];  bh[np * 2 + 1][1] = r4[3];
            }
            #pragma unroll
            for (int mt = 0; mt < 2; mt++) {
                uint32_t ah[4];
                ldmatrix_x4(ah, st + aOffBase + kadd + (uint32_t)(mt * 16 * 80));
                #pragma unroll
                for (int nt = 0; nt < 4; nt++)
                    mma16816(acc[mt][nt], ah, bh[nt]);
            }
        }
    }

    #pragma unroll
    for (int mt = 0; mt < 2; mt++) {
        int r = m0 + wm * 32 + mt * 16 + g;
        #pragma unroll
        for (int nt = 0; nt < 4; nt++) {
            int c = n0 + wn * 32 + nt * 8 + tig * 2;
            if (MODE == 1) {
                float2 v0, v1;
                v0.x = acc[mt][nt][0] * outscale + bias[c];
                v0.y = acc[mt][nt][1] * outscale + bias[c + 1];
                v1.x = acc[mt][nt][2] * outscale + bias[c];
                v1.y = acc[mt][nt][3] * outscale + bias[c + 1];
                *(float2*)(out + (size_t)r * CH + c)       = v0;
                *(float2*)(out + (size_t)(r + 8) * CH + c) = v1;
            } else {
                #pragma unroll
                for (int hr = 0; hr < 2; hr++) {
                    __half hx = __float2half_rn(acc[mt][nt][hr * 2]);
                    __half hy = __float2half_rn(acc[mt][nt][hr * 2 + 1]);
                    size_t idx = (size_t)(r + hr * 8) * CH + c;
                    *(__half2*)(outhi + idx) = __halves2half2(hx, hy);
                }
            }
        }
    }
}

// ================= circulant attention (1-product, cp.async 4-stage V) =======
// bsel: which batch this launch handles (grid z = 1).
#define CIRC_STAGE_BYTES 9216
#define CIRC_SMEM_BYTES (16384 + 4 * CIRC_STAGE_BYTES)

__global__ void __launch_bounds__(256, 2) circ_mma_kernel(int bsel) {
    extern __shared__ __half dsmh[];
    __half* A2hi  = dsmh;
    __half* A2hiS = dsmh + 4096;
    uint32_t sVu32 = smem_u32(dsmh + 8192);

    int tid = threadIdx.x;
    int i0 = blockIdx.x * 128;
    int h  = blockIdx.y;
    int b  = bsel;
    int c0 = h * HDIM;
    int w = tid >> 5, lane = tid & 31;
    int wm = w >> 2, wn = w & 3;
    int g = lane >> 2, tig = lane & 3;

    const float* arow = g_attn + (size_t)(b * HEADS + h) * SEQ;
    for (int t = tid; t < SEQ; t += 256) {
        __half hi = __float2half_rn(arow[t] * OA_SCALE);
        A2hi[t] = hi;  A2hi[t + SEQ] = hi;
    }
    __syncthreads();
    for (int t = tid; t < 2 * SEQ - 1; t += 256) A2hiS[t] = A2hi[t + 1];
    if (tid == 0) A2hiS[2 * SEQ - 1] = __float2half_rn(0.f);

    int ob = SEQ + 2 * tig - (i0 + wm * 64 + g);
    int par = ob & 1;
    const uint32_t* PhiBase = (const uint32_t*)(par ? A2hiS : A2hi) + ((ob - par) >> 1);

    int vrow = tid >> 3, vcg = tid & 7;
    const __half* gvh = g_vhi + ((size_t)b * SEQ + vrow) * CH + c0 + vcg * 8;
    uint32_t svoA = (uint32_t)((vrow * 72 + vcg * 8) * 2);
    uint32_t svoB = (uint32_t)(((vrow + 32) * 72 + vcg * 8) * 2);

    int mrow = ((lane >> 3) & 1) * 8 + (lane & 7);
    int ncol = wn * 16 + (lane >> 4) * 8;
    uint32_t svAddrPart = (uint32_t)(mrow * 144 + ncol * 2);

    float acc[4][2][4];
    #pragma unroll
    for (int mt = 0; mt < 4; mt++)
        #pragma unroll
        for (int nt = 0; nt < 2; nt++)
            #pragma unroll
            for (int r = 0; r < 4; r++) acc[mt][nt][r] = 0.f;

    #pragma unroll
    for (int p = 0; p < 3; p++) {
        uint32_t st = sVu32 + (uint32_t)p * CIRC_STAGE_BYTES;
        size_t adv = (size_t)p * 64 * CH;
        cp_async16(st + svoA, gvh + adv);
        cp_async16(st + svoB, gvh + adv + 32 * CH);
        CP_COMMIT();
    }
    __syncthreads();

    const int NCHUNK = SEQ / 64;   // 32
    for (int c = 0; c < NCHUNK; c++) {
        if (c + 2 < NCHUNK)      { CP_WAIT(2); }
        else if (c + 1 < NCHUNK) { CP_WAIT(1); }
        else                     { CP_WAIT(0); }
        __syncthreads();

        if (c + 3 < NCHUNK) {
            uint32_t st = sVu32 + (uint32_t)((c + 3) & 3) * CIRC_STAGE_BYTES;
            size_t adv = (size_t)(c + 3) * 64 * CH;
            cp_async16(st + svoA, gvh + adv);
            cp_async16(st + svoB, gvh + adv + 32 * CH);
            CP_COMMIT();
        }

        const uint32_t* Phi = PhiBase + 32 * c;
        uint32_t ehi[7], fhi[8];
        #pragma unroll
        for (int t = 0; t < 7; t++) ehi[t] = Phi[8 * t - 24];
        #pragma unroll
        for (int t = 0; t < 8; t++) fhi[t] = Phi[8 * t - 28];

        uint32_t sVAddr = sVu32 + (uint32_t)(c & 3) * CIRC_STAGE_BYTES + svAddrPart;

        #pragma unroll
        for (int kk = 0; kk < 4; kk++) {
            uint32_t bh[4];
            ldmatrix_x4_trans(bh, sVAddr + kk * 2304u);
            #pragma unroll
            for (int mt = 0; mt < 4; mt++) {
                int d3 = kk - mt + 3;
                uint32_t ah[4] = {ehi[d3], fhi[d3], fhi[d3 + 1], ehi[d3]};
                mma16816(acc[mt][0], ah, bh);
                uint32_t bh1[2] = {bh[2], bh[3]};
                mma16816(acc[mt][1], ah, bh1);
            }
        }
    }

    #pragma unroll
    for (int mt = 0; mt < 4; mt++) {
        int r = i0 + wm * 64 + mt * 16 + g;
        #pragma unroll
        for (int nt = 0; nt < 2; nt++) {
            int cc = c0 + wn * 16 + nt * 8 + tig * 2;
            #pragma unroll
            for (int hr = 0; hr < 2; hr++) {
                __half hx = __float2half_rn(acc[mt][nt][hr * 2]);
                __half hy = __float2half_rn(acc[mt][nt][hr * 2 + 1]);
                size_t idx = (size_t)(b * SEQ + r + hr * 8) * CH + cc;
                *(__half2*)(g_oahi + idx) = __halves2half2(hx, hy);
            }
        }
    }
}

// ---------------- launch ------------------------------------------------------
extern "C" void kernel_launch(void* const* d_in, const int* in_sizes, int n_in,
                              void* d_out, int out_size) {
    const float* x  = (const float*)d_in[0];
    const float* Wq = (const float*)d_in[1];
    const float* Wk = (const float*)d_in[2];
    const float* Wv = (const float*)d_in[3];
    const float* Wp = (const float*)d_in[4];
    const float* bp = (const float*)d_in[5];
    float* out = (float*)d_out;

    __half* dxhi; cudaGetSymbolAddress((void**)&dxhi,  g_xhi);
    __half* dvhi; cudaGetSymbolAddress((void**)&dvhi,  g_wvhi);
    __half* dphi; cudaGetSymbolAddress((void**)&dphi,  g_wphi);
    __half* dVhi; cudaGetSymbolAddress((void**)&dVhi,  g_vhi);
    __half* dohi; cudaGetSymbolAddress((void**)&dohi,  g_oahi);

    static cudaStream_t s1 = nullptr;
    static cudaEvent_t evX = nullptr, evV = nullptr, evC0 = nullptr, evG0 = nullptr;
    if (!s1) {
        cudaStreamCreateWithFlags(&s1, cudaStreamNonBlocking);
        cudaEventCreateWithFlags(&evX,  cudaEventDisableTiming);
        cudaEventCreateWithFlags(&evV,  cudaEventDisableTiming);
        cudaEventCreateWithFlags(&evC0, cudaEventDisableTiming);
        cudaEventCreateWithFlags(&evG0, cudaEventDisableTiming);
        cudaFuncSetAttribute(circ_mma_kernel,
                             cudaFuncAttributeMaxDynamicSharedMemorySize, CIRC_SMEM_BYTES);
        cudaFuncSetAttribute(gemm_mma_kernel<1>,
                             cudaFuncAttributeMaxDynamicSharedMemorySize, GEMM_SMEM_BYTES);
        cudaFuncSetAttribute(gemm_mma_kernel<2>,
                             cudaFuncAttributeMaxDynamicSharedMemorySize, GEMM_SMEM_BYTES);
    }

    int n4w = CH * CH / 4;
    // side stream: weight conversions (concurrent with xhi_part)
    wvp_hi_kernel<<<dim3((n4w + 255) / 256, 2), 256, 0, s1>>>(Wv, Wp, n4w);
    // main: x conversion + partials
    xhi_part_kernel<<<dim3(128, BATCH), CH>>>(x);
    cudaEventRecord(evX, 0);

    // side stream: V projection after both conversions
    cudaStreamWaitEvent(s1, evX, 0);
    gemm_mma_kernel<2><<<dim3(CH / 128, (BATCH * SEQ) / 64), 256, GEMM_SMEM_BYTES, s1>>>(
        dxhi, dvhi, nullptr, nullptr, dVhi, 1.0f, 0);
    cudaEventRecord(evV, s1);

    // main (concurrent with gemm_V): u-chain
    xmean2_kernel<<<dim3(8, BATCH), CH>>>();
    kavg_kernel<<<BATCH * HEADS, 256>>>(Wk);
    u2_kernel<<<dim3(CH / 256, BATCH * HEADS), 256>>>(Wq);
    z_kernel<<<dim3(SEQ / 8, BATCH), 256>>>(x);
    softmax_kernel<<<BATCH * HEADS, 256>>>();

    // join, then batch-split pipeline: circ(b0) -> [gemm1(b0) || circ(b1)] -> gemm1(b1)
    cudaStreamWaitEvent(0, evV, 0);
    circ_mma_kernel<<<dim3(SEQ / 128, HEADS), 256, CIRC_SMEM_BYTES>>>(0);
    cudaEventRecord(evC0, 0);

    cudaStreamWaitEvent(s1, evC0, 0);
    gemm_mma_kernel<1><<<dim3(CH / 128, SEQ / 64), 256, GEMM_SMEM_BYTES, s1>>>(
        dohi, dphi, bp, out, nullptr, OA_INV, 0);
    cudaEventRecord(evG0, s1);

    circ_mma_kernel<<<dim3(SEQ / 128, HEADS), 256, CIRC_SMEM_BYTES>>>(1);
    gemm_mma_kernel<1><<<dim3(CH / 128, SEQ / 64), 256, GEMM_SMEM_BYTES>>>(
        dohi, dphi, bp, out, nullptr, OA_INV, SEQ);

    // join side stream back into capture origin
    cudaStreamWaitEvent(0, evG0, 0);
}